// round 16
// baseline (speedup 1.0000x reference)
#include <cuda_runtime.h>
#include <math.h>

// Problem constants
#define B_   2048
#define T_   256
#define DA_  20
#define NCH  32      // number of time chunks (== warp lanes in boundary scans)
#define CL   8       // chunk length (NCH*CL == T_)

#define QD   0.08f
#define RINV (1.0f/0.03f)

// Scratch (static __device__ globals). Packed float4, layout [t][group][b]
// so warp lanes (consecutive b) give coalesced 128B transactions.
__device__ float4 g_ua [T_ * 2 * B_];    // 0 = u/R | 1 = (a0,a1,a2,0)              (16 MB)
__device__ float4 g_fc [NCH * 12 * B_];  // fwd chunk element: A rows(4), b(1), C sym(3), eta(1), J sym(3)
__device__ float4 g_fb [NCH * 4 * B_];   // fwd boundary state: m(1), P sym(3)
__device__ float4 g_fwd[T_ * 4 * B_];    // 0=post_z | 1-3=post_std sym10+pad       (32 MB)
__device__ float4 g_ch [NCH * 8 * B_];   // smoother chunk map: M rows(4), c(1), E sym(3)
__device__ float4 g_bd [NCH * 5 * B_];   // smoother boundary: z(1), S rows(4)

// ---------------------------------------------------------------------------
// 4x4 helpers (row-major flat)
// ---------------------------------------------------------------------------
__device__ __forceinline__ void mm4(const float* A, const float* B, float* C) {
#pragma unroll
    for (int i = 0; i < 4; i++)
#pragma unroll
        for (int j = 0; j < 4; j++) {
            float s = A[i*4+0] * B[0*4+j];
            s = fmaf(A[i*4+1], B[1*4+j], s);
            s = fmaf(A[i*4+2], B[2*4+j], s);
            s = fmaf(A[i*4+3], B[3*4+j], s);
            C[i*4+j] = s;
        }
}

// C = A * B^T, result known symmetric: upper triangle + mirror.
__device__ __forceinline__ void mmT4_symf(const float* A, const float* B, float* C) {
#pragma unroll
    for (int i = 0; i < 4; i++)
#pragma unroll
        for (int j = i; j < 4; j++) {
            float s = A[i*4+0] * B[j*4+0];
            s = fmaf(A[i*4+1], B[j*4+1], s);
            s = fmaf(A[i*4+2], B[j*4+2], s);
            s = fmaf(A[i*4+3], B[j*4+3], s);
            C[i*4+j] = s;
        }
    C[4]  = C[1];  C[8]  = C[2];  C[12] = C[3];
    C[9]  = C[6];  C[13] = C[7];  C[14] = C[11];
}

// C = A^T * U, result known symmetric.
__device__ __forceinline__ void mtm_sym(const float* A, const float* U, float* C) {
#pragma unroll
    for (int i = 0; i < 4; i++)
#pragma unroll
        for (int j = i; j < 4; j++) {
            float s = A[0*4+i] * U[0*4+j];
            s = fmaf(A[1*4+i], U[1*4+j], s);
            s = fmaf(A[2*4+i], U[2*4+j], s);
            s = fmaf(A[3*4+i], U[3*4+j], s);
            C[i*4+j] = s;
        }
    C[4]  = C[1];  C[8]  = C[2];  C[12] = C[3];
    C[9]  = C[6];  C[13] = C[7];  C[14] = C[11];
}

__device__ __forceinline__ void mv4(const float* A, const float* x, float* y) {
#pragma unroll
    for (int i = 0; i < 4; i++) {
        float s = A[i*4+0] * x[0];
        s = fmaf(A[i*4+1], x[1], s);
        s = fmaf(A[i*4+2], x[2], s);
        s = fmaf(A[i*4+3], x[3], s);
        y[i] = s;
    }
}

// y = A^T x
__device__ __forceinline__ void mvT4(const float* A, const float* x, float* y) {
#pragma unroll
    for (int i = 0; i < 4; i++) {
        float s = A[0*4+i] * x[0];
        s = fmaf(A[1*4+i], x[1], s);
        s = fmaf(A[2*4+i], x[2], s);
        s = fmaf(A[3*4+i], x[3], s);
        y[i] = s;
    }
}

// General branch-free 4x4 inverse via 2x2 sub-determinants.
__device__ __forceinline__ void inv4(const float* a, float* inv) {
    float b00 = a[0]*a[5]  - a[1]*a[4];
    float b01 = a[0]*a[6]  - a[2]*a[4];
    float b02 = a[0]*a[7]  - a[3]*a[4];
    float b03 = a[1]*a[6]  - a[2]*a[5];
    float b04 = a[1]*a[7]  - a[3]*a[5];
    float b05 = a[2]*a[7]  - a[3]*a[6];
    float b06 = a[8]*a[13] - a[9]*a[12];
    float b07 = a[8]*a[14] - a[10]*a[12];
    float b08 = a[8]*a[15] - a[11]*a[12];
    float b09 = a[9]*a[14] - a[10]*a[13];
    float b10 = a[9]*a[15] - a[11]*a[13];
    float b11 = a[10]*a[15]- a[11]*a[14];
    float det = b00*b11 - b01*b10 + b02*b09 + b03*b08 - b04*b07 + b05*b06;
    float id = 1.0f / det;
    inv[0]  = (a[5]*b11  - a[6]*b10  + a[7]*b09 ) * id;
    inv[1]  = (a[2]*b10  - a[1]*b11  - a[3]*b09 ) * id;
    inv[2]  = (a[13]*b05 - a[14]*b04 + a[15]*b03) * id;
    inv[3]  = (a[10]*b04 - a[9]*b05  - a[11]*b03) * id;
    inv[4]  = (a[6]*b08  - a[4]*b11  - a[7]*b07 ) * id;
    inv[5]  = (a[0]*b11  - a[2]*b08  + a[3]*b07 ) * id;
    inv[6]  = (a[14]*b02 - a[12]*b05 - a[15]*b01) * id;
    inv[7]  = (a[8]*b05  - a[10]*b02 + a[11]*b01) * id;
    inv[8]  = (a[4]*b10  - a[5]*b08  + a[7]*b06 ) * id;
    inv[9]  = (a[1]*b08  - a[0]*b10  - a[3]*b06 ) * id;
    inv[10] = (a[12]*b04 - a[13]*b02 + a[15]*b00) * id;
    inv[11] = (a[9]*b02  - a[8]*b04  - a[11]*b00) * id;
    inv[12] = (a[5]*b07  - a[4]*b09  - a[6]*b06 ) * id;
    inv[13] = (a[0]*b09  - a[1]*b07  + a[2]*b06 ) * id;
    inv[14] = (a[13]*b01 - a[12]*b03 - a[14]*b00) * id;
    inv[15] = (a[8]*b03  - a[9]*b01  + a[10]*b00) * id;
}

// SPD 4x4 inverse via 2x2 block Schur complement.
__device__ __forceinline__ void syminv4(const float* a, float* r) {
    float dP  = fmaf(a[0], a[5], -a[1]*a[1]);
    float idP = 1.0f / dP;
    float p00 =  a[5]*idP, p01 = -a[1]*idP, p11 = a[0]*idP;
    float t00 = fmaf(p00, a[2], p01*a[6]);
    float t01 = fmaf(p00, a[3], p01*a[7]);
    float t10 = fmaf(p01, a[2], p11*a[6]);
    float t11 = fmaf(p01, a[3], p11*a[7]);
    float s00 = a[10] - fmaf(a[2], t00, a[6]*t10);
    float s01 = a[11] - fmaf(a[2], t01, a[6]*t11);
    float s11 = a[15] - fmaf(a[3], t01, a[7]*t11);
    float dS  = fmaf(s00, s11, -s01*s01);
    float idS = 1.0f / dS;
    float w00 = s11*idS, w01 = -s01*idS, w11 = s00*idS;
    float u00 = fmaf(t00, w00, t01*w01);
    float u01 = fmaf(t00, w01, t01*w11);
    float u10 = fmaf(t10, w00, t11*w01);
    float u11 = fmaf(t10, w01, t11*w11);
    float x00 = p00 + fmaf(u00, t00, u01*t01);
    float x01 = p01 + fmaf(u00, t10, u01*t11);
    float x11 = p11 + fmaf(u10, t10, u11*t11);
    r[0]=x00;  r[1]=x01;  r[4]=x01;  r[5]=x11;
    r[2]=-u00; r[3]=-u01; r[6]=-u10; r[7]=-u11;
    r[8]=-u00; r[9]=-u10; r[12]=-u01; r[13]=-u11;
    r[10]=w00; r[11]=w01; r[14]=w01; r[15]=w11;
}

__device__ __forceinline__ void unpack_sym10(float4 f1, float4 f2, float4 f3, float* M) {
    M[0]=f1.x;  M[1]=f1.y;  M[2]=f1.z;  M[3]=f1.w;
    M[4]=f1.y;  M[5]=f2.x;  M[6]=f2.y;  M[7]=f2.z;
    M[8]=f1.z;  M[9]=f2.y;  M[10]=f2.w; M[11]=f3.x;
    M[12]=f1.w; M[13]=f2.z; M[14]=f3.x; M[15]=f3.y;
}

__device__ __forceinline__ void unpack_rows(float4 r0, float4 r1, float4 r2, float4 r3, float* M) {
    M[0]=r0.x;  M[1]=r0.y;  M[2]=r0.z;  M[3]=r0.w;
    M[4]=r1.x;  M[5]=r1.y;  M[6]=r1.z;  M[7]=r1.w;
    M[8]=r2.x;  M[9]=r2.y;  M[10]=r2.z; M[11]=r2.w;
    M[12]=r3.x; M[13]=r3.y; M[14]=r3.z; M[15]=r3.w;
}

// ---------------------------------------------------------------------------
// Shared-memory setup for consumers: sA = A_base (48), sM = 6 Gram combos (96)
// ---------------------------------------------------------------------------
__device__ __forceinline__ void setup_shared(const float* __restrict__ Ab,
                                             const float* __restrict__ Cb,
                                             float* sA, float* sM) {
    for (int i = threadIdx.x; i < 48; i += blockDim.x) sA[i] = Ab[i];
    if (threadIdx.x < 96) {
        int e = threadIdx.x;
        int m = e >> 4, idx = e & 15, j1 = idx >> 2, j2 = idx & 3;
        int k, l;
        switch (m) {
            case 0: k=0; l=0; break;  case 1: k=1; l=1; break;
            case 2: k=2; l=2; break;  case 3: k=0; l=1; break;
            case 4: k=0; l=2; break;  default: k=1; l=2; break;
        }
        float s = 0.0f;
        for (int i = 0; i < DA_; i++)
            s = fmaf(Cb[k*80+i*4+j1], Cb[l*80+i*4+j2], s);
        if (k != l)
            for (int i = 0; i < DA_; i++)
                s = fmaf(Cb[l*80+i*4+j1], Cb[k*80+i*4+j2], s);
        sM[e] = s;
    }
    __syncthreads();
}

// Reconstruct Ai from alphas.
__device__ __forceinline__ void make_Ai(const float* sA, float a0, float a1, float a2, float* Ai) {
#pragma unroll
    for (int i = 0; i < 16; i++)
        Ai[i] = fmaf(a0, sA[i], fmaf(a1, sA[16+i], a2 * sA[32+i]));
}

// Reconstruct Cr (symmetric) from alphas.
__device__ __forceinline__ void make_Cr(const float* sM, float a0, float a1, float a2, float* Cr) {
    float c0 = a0*a0*RINV, c1 = a1*a1*RINV, c2 = a2*a2*RINV;
    float c3 = a0*a1*RINV, c4 = a0*a2*RINV, c5 = a1*a2*RINV;
    const int SI[10] = {0, 1, 2, 3, 5, 6, 7, 10, 11, 15};
#pragma unroll
    for (int u = 0; u < 10; u++) {
        int i = SI[u];
        Cr[i] = fmaf(c0, sM[i],
                fmaf(c1, sM[16+i],
                fmaf(c2, sM[32+i],
                fmaf(c3, sM[48+i],
                fmaf(c4, sM[64+i], c5 * sM[80+i])))));
    }
    Cr[4]  = Cr[1];  Cr[8]  = Cr[2];  Cr[12] = Cr[3];
    Cr[9]  = Cr[6];  Cr[13] = Cr[7];  Cr[14] = Cr[11];
}

// Load (u, Ai, Cr) for (t, b): 32B load + on-the-fly reconstruction.
__device__ __forceinline__ void load_pre(int t, int b, const float* sA, const float* sM,
                                         float* u, float* Ai, float* Cr) {
    int base = (t * 2) * B_ + b;
    float4 u4 = g_ua[base];
    float4 a4 = g_ua[base + B_];
    u[0]=u4.x; u[1]=u4.y; u[2]=u4.z; u[3]=u4.w;
    make_Ai(sA, a4.x, a4.y, a4.z, Ai);
    make_Cr(sM, a4.x, a4.y, a4.z, Cr);
}

// ---------------------------------------------------------------------------
// Kernel 1: per-(b,t): softmax, u = C^T a / R  (compressed 32B output)
// ---------------------------------------------------------------------------
__global__ void pre_kernel(const float* __restrict__ a,
                           const float* __restrict__ lg,
                           const float* __restrict__ Cb) {
    __shared__ float sC[240];
    for (int i = threadIdx.x; i < 240; i += 256) sC[i] = Cb[i];
    __syncthreads();

    int tid = blockIdx.x * 256 + threadIdx.x;
    int t = tid / B_;
    int b = tid - t * B_;

    const float* lp = lg + ((size_t)b * T_ + t) * 3;
    float l0 = lp[0], l1 = lp[1], l2 = lp[2];
    float mx = fmaxf(l0, fmaxf(l1, l2));
    float e0 = expf(l0 - mx), e1 = expf(l1 - mx), e2 = expf(l2 - mx);
    float is = 1.0f / (e0 + e1 + e2);
    float a0 = e0 * is, a1 = e1 * is, a2 = e2 * is;

    const float4* ap4 = reinterpret_cast<const float4*>(a + ((size_t)b * T_ + t) * DA_);
    float av[20];
#pragma unroll
    for (int q = 0; q < 5; q++) {
        float4 v = ap4[q];
        av[q*4+0] = v.x; av[q*4+1] = v.y; av[q*4+2] = v.z; av[q*4+3] = v.w;
    }
    float u0 = 0.f, u1 = 0.f, u2 = 0.f, u3 = 0.f;
#pragma unroll
    for (int i = 0; i < DA_; i++) {
        float w0 = fmaf(a0, sC[i*4+0], fmaf(a1, sC[80+i*4+0], a2 * sC[160+i*4+0]));
        float w1 = fmaf(a0, sC[i*4+1], fmaf(a1, sC[80+i*4+1], a2 * sC[160+i*4+1]));
        float w2 = fmaf(a0, sC[i*4+2], fmaf(a1, sC[80+i*4+2], a2 * sC[160+i*4+2]));
        float w3 = fmaf(a0, sC[i*4+3], fmaf(a1, sC[80+i*4+3], a2 * sC[160+i*4+3]));
        u0 = fmaf(av[i], w0, u0);
        u1 = fmaf(av[i], w1, u1);
        u2 = fmaf(av[i], w2, u2);
        u3 = fmaf(av[i], w3, u3);
    }

    int base = (t * 2) * B_ + b;
    g_ua[base + 0*B_] = make_float4(u0*RINV, u1*RINV, u2*RINV, u3*RINV);
    g_ua[base + 1*B_] = make_float4(a0, a1, a2, 0.f);
}

// ---------------------------------------------------------------------------
// Build forward-scan element (A, b, C, eta, J) for time t.
// ---------------------------------------------------------------------------
__device__ __forceinline__ void build_element(int t, int b,
        const float* sA, const float* sM,
        float* A, float* bb, float* C, float* eta, float* J) {
    float u[4], Ai[16], Cr[16];
    load_pre(t, b, sA, sM, u, Ai, Cr);

    if (t == 0) {
        float S[16]; mmT4_symf(Ai, Ai, S);      // Ai Ai^T
        float Ph[16];
#pragma unroll
        for (int i = 0; i < 16; i++) Ph[i] = 20.0f * S[i];
        Ph[0] += QD; Ph[5] += QD; Ph[10] += QD; Ph[15] += QD;
        float Phi[16]; syminv4(Ph, Phi);
        float Ms[16];
#pragma unroll
        for (int i = 0; i < 16; i++) Ms[i] = Phi[i] + Cr[i];
        float W[16]; syminv4(Ms, W);
        mv4(W, u, bb);
#pragma unroll
        for (int i = 0; i < 16; i++) { A[i] = 0.f; C[i] = W[i]; J[i] = 0.f; }
#pragma unroll
        for (int i = 0; i < 4; i++) eta[i] = 0.f;
        return;
    }

    float M[16];
#pragma unroll
    for (int i = 0; i < 16; i++) M[i] = QD * Cr[i];
    M[0] += 1.f; M[5] += 1.f; M[10] += 1.f; M[15] += 1.f;
    float G[16]; syminv4(M, G);

    float v[4]; mv4(G, u, v);
#pragma unroll
    for (int i = 0; i < 4; i++) bb[i] = QD * v[i];
    mm4(G, Ai, A);
    mvT4(Ai, v, eta);
#pragma unroll
    for (int i = 0; i < 16; i++) C[i] = QD * G[i];
    float X[16]; mm4(G, Cr, X);
    float U[16]; mm4(X, Ai, U);
    mtm_sym(Ai, U, J);
}

// ---------------------------------------------------------------------------
// Compose: acc = acc (earlier) ⊗ e (later).   [Särkkä & García-Fernández]
// ---------------------------------------------------------------------------
__device__ __forceinline__ void compose_fwd(
        float* Ai_, float* bi, float* Ci, float* ni, float* Ji,      // acc (i)
        const float* Aj, const float* bj, const float* Cj,
        const float* nj, const float* Jj) {                          // elem (j)
    float M1[16]; mm4(Ci, Jj, M1);
    M1[0] += 1.f; M1[5] += 1.f; M1[10] += 1.f; M1[15] += 1.f;
    float dn[16]; inv4(M1, dn);
    float T1[16]; mm4(Aj, dn, T1);

    float An[16]; mm4(T1, Ai_, An);

    float w1[4]; mv4(Ci, nj, w1);
#pragma unroll
    for (int i = 0; i < 4; i++) w1[i] += bi[i];
    float bn[4]; mv4(T1, w1, bn);
#pragma unroll
    for (int i = 0; i < 4; i++) bn[i] += bj[i];

    float X[16]; mm4(T1, Ci, X);
    float Cn[16]; mmT4_symf(X, Aj, Cn);
#pragma unroll
    for (int i = 0; i < 16; i++) Cn[i] += Cj[i];

    // G = (I + Jj Ci)^-1 = I - Jj dn Ci
    float Y[16]; mm4(Jj, dn, Y);
    float G[16]; mm4(Y, Ci, G);
#pragma unroll
    for (int i = 0; i < 16; i++) G[i] = -G[i];
    G[0] += 1.f; G[5] += 1.f; G[10] += 1.f; G[15] += 1.f;

    float w2[4]; mv4(Jj, bi, w2);
#pragma unroll
    for (int i = 0; i < 4; i++) w2[i] = nj[i] - w2[i];
    float w3[4]; mv4(G, w2, w3);
    float nn[4]; mvT4(Ai_, w3, nn);
#pragma unroll
    for (int i = 0; i < 4; i++) nn[i] += ni[i];

    float Z[16]; mm4(G, Jj, Z);
    float U[16]; mm4(Z, Ai_, U);
    float Jn[16]; mtm_sym(Ai_, U, Jn);
#pragma unroll
    for (int i = 0; i < 16; i++) Jn[i] += Ji[i];

#pragma unroll
    for (int i = 0; i < 16; i++) { Ai_[i] = An[i]; Ci[i] = Cn[i]; Ji[i] = Jn[i]; }
#pragma unroll
    for (int i = 0; i < 4; i++)  { bi[i] = bn[i]; ni[i] = nn[i]; }
}

// ---------------------------------------------------------------------------
// Kernel 2: compose the CL elements of each chunk. Chunk NCH-1's element is
// never consumed by the boundary scan, so only NCH-1 chunks are built.
// ---------------------------------------------------------------------------
__global__ void __launch_bounds__(128, 3)
fchunk_kernel(const float* __restrict__ Ab, const float* __restrict__ Cb) {
    __shared__ float sA[48];
    __shared__ float sM[96];
    setup_shared(Ab, Cb, sA, sM);

    int tid = blockIdx.x * blockDim.x + threadIdx.x;
    int k = tid / B_;                 // 0 .. NCH-2
    int b = tid - k * B_;
    int t0 = k * CL;

    float A[16], bb[4], C[16], eta[4], J[16];
    build_element(t0, b, sA, sM, A, bb, C, eta, J);
#pragma unroll 1
    for (int s = 1; s < CL; s++) {
        float Aj[16], bj[4], Cj[16], nj[4], Jj[16];
        build_element(t0 + s, b, sA, sM, Aj, bj, Cj, nj, Jj);
        compose_fwd(A, bb, C, eta, J, Aj, bj, Cj, nj, Jj);
    }

    int cb = (k * 12) * B_ + b;
    g_fc[cb + 0*B_]  = make_float4(A[0],  A[1],  A[2],  A[3]);
    g_fc[cb + 1*B_]  = make_float4(A[4],  A[5],  A[6],  A[7]);
    g_fc[cb + 2*B_]  = make_float4(A[8],  A[9],  A[10], A[11]);
    g_fc[cb + 3*B_]  = make_float4(A[12], A[13], A[14], A[15]);
    g_fc[cb + 4*B_]  = make_float4(bb[0], bb[1], bb[2], bb[3]);
    g_fc[cb + 5*B_]  = make_float4(C[0],  C[1],  C[2],  C[3]);
    g_fc[cb + 6*B_]  = make_float4(C[5],  C[6],  C[7],  C[10]);
    g_fc[cb + 7*B_]  = make_float4(C[11], C[15], 0.f,  0.f);
    g_fc[cb + 8*B_]  = make_float4(eta[0], eta[1], eta[2], eta[3]);
    g_fc[cb + 9*B_]  = make_float4(J[0],  J[1],  J[2],  J[3]);
    g_fc[cb + 10*B_] = make_float4(J[5],  J[6],  J[7],  J[10]);
    g_fc[cb + 11*B_] = make_float4(J[11], J[15], 0.f,  0.f);
}

// ---------------------------------------------------------------------------
// Kernel 3: Kogge-Stone warp scan over chunk elements -> state entering each
// chunk. One warp per batch; lane k holds: prior (lane 0) or element of
// chunk k-1 (lanes 1..31). Inclusive scan at lane k = prior ∘ e_0..e_{k-1};
// because the prior element has A=0 and J=0, (b, C) IS the filtered (m, P).
// ---------------------------------------------------------------------------
__global__ void fboundary_ks_kernel() {
    int lane = threadIdx.x & 31;
    int b = (blockIdx.x * blockDim.x + threadIdx.x) >> 5;

    float A[16], bb[4], C[16], eta[4], J[16];
    if (lane == 0) {
#pragma unroll
        for (int i = 0; i < 16; i++) {
            A[i] = 0.f; J[i] = 0.f;
            C[i] = (i % 5 == 0) ? 20.0f : 0.0f;
        }
#pragma unroll
        for (int i = 0; i < 4; i++) { bb[i] = 0.f; eta[i] = 0.f; }
    } else {
        int cb = ((lane - 1) * 12) * B_ + b;
        unpack_rows(g_fc[cb], g_fc[cb+B_], g_fc[cb+2*B_], g_fc[cb+3*B_], A);
        float4 b4 = g_fc[cb+4*B_];
        bb[0]=b4.x; bb[1]=b4.y; bb[2]=b4.z; bb[3]=b4.w;
        unpack_sym10(g_fc[cb+5*B_], g_fc[cb+6*B_], g_fc[cb+7*B_], C);
        float4 n4 = g_fc[cb+8*B_];
        eta[0]=n4.x; eta[1]=n4.y; eta[2]=n4.z; eta[3]=n4.w;
        unpack_sym10(g_fc[cb+9*B_], g_fc[cb+10*B_], g_fc[cb+11*B_], J);
    }

#pragma unroll
    for (int d = 1; d < 32; d <<= 1) {
        float oA[16], ob[4], oC[16], oe[4], oJ[16];
#pragma unroll
        for (int i = 0; i < 16; i++) {
            oA[i] = __shfl_up_sync(0xffffffffu, A[i], d);
            oC[i] = __shfl_up_sync(0xffffffffu, C[i], d);
            oJ[i] = __shfl_up_sync(0xffffffffu, J[i], d);
        }
#pragma unroll
        for (int i = 0; i < 4; i++) {
            ob[i] = __shfl_up_sync(0xffffffffu, bb[i], d);
            oe[i] = __shfl_up_sync(0xffffffffu, eta[i], d);
        }
        if (lane >= d) {
            compose_fwd(oA, ob, oC, oe, oJ, A, bb, C, eta, J);
#pragma unroll
            for (int i = 0; i < 16; i++) { A[i] = oA[i]; C[i] = oC[i]; J[i] = oJ[i]; }
#pragma unroll
            for (int i = 0; i < 4; i++)  { bb[i] = ob[i]; eta[i] = oe[i]; }
        }
    }

    // state entering chunk `lane`: m = bb, P = C
    int db = (lane * 4) * B_ + b;
    g_fb[db + 0*B_] = make_float4(bb[0], bb[1], bb[2], bb[3]);
    g_fb[db + 1*B_] = make_float4(C[0],  C[1],  C[2],  C[3]);
    g_fb[db + 2*B_] = make_float4(C[5],  C[6],  C[7],  C[10]);
    g_fb[db + 3*B_] = make_float4(C[11], C[15], 0.f,  0.f);
}

// ---------------------------------------------------------------------------
// Smoother step coefficients from (pz_t, W_t, alpha_{t+1}):
//   z_s(t) = D z_s(t+1) + c ;  S_s(t) = D S_s(t+1) D^T + E
// ---------------------------------------------------------------------------
__device__ __forceinline__ void make_DcE(int t, int b, const float* sA,
        const float* pz, const float* W, float* D, float* c, float* E) {
    if (t == T_ - 1) {
#pragma unroll
        for (int i = 0; i < 16; i++) { D[i] = 0.f; E[i] = W[i]; }
#pragma unroll
        for (int i = 0; i < 4; i++) c[i] = pz[i];
        return;
    }
    float4 a4 = g_ua[((t + 1) * 2 + 1) * B_ + b];
    float Ai1[16]; make_Ai(sA, a4.x, a4.y, a4.z, Ai1);

    float APs[16]; mm4(Ai1, W, APs);
    float shn[16]; mmT4_symf(APs, Ai1, shn);
    shn[0] += QD; shn[5] += QD; shn[10] += QD; shn[15] += QD;
#pragma unroll
    for (int i = 0; i < 16; i++)
        shn[i] = fmaxf(shn[i], (i % 5 == 0) ? 1e-4f : 0.0f);

    float iv[16]; inv4(shn, iv);
    // D = W Ai1^T iv = APs^T iv
#pragma unroll
    for (int i = 0; i < 4; i++)
#pragma unroll
        for (int j = 0; j < 4; j++) {
            float s = APs[0*4+i] * iv[0*4+j];
            s = fmaf(APs[1*4+i], iv[1*4+j], s);
            s = fmaf(APs[2*4+i], iv[2*4+j], s);
            s = fmaf(APs[3*4+i], iv[3*4+j], s);
            D[i*4+j] = s;
        }
    float zhn[4]; mv4(Ai1, pz, zhn);
    float tz[4];  mv4(D, zhn, tz);
#pragma unroll
    for (int i = 0; i < 4; i++) c[i] = pz[i] - tz[i];

    float X[16]; mm4(D, shn, X);
    float Y[16]; mmT4_symf(X, D, Y);
#pragma unroll
    for (int i = 0; i < 16; i++) E[i] = W[i] - Y[i];
}

// ---------------------------------------------------------------------------
// Kernel 4 (fused): from chunk entry state run exact sequential filter steps,
// write (pz, W), and compose the smoother chunk affine map (skipped for
// chunk 0 -- its map is never applied).
// ---------------------------------------------------------------------------
__global__ void __launch_bounds__(128, 3)
ffinal_schunk_kernel(const float* __restrict__ Ab, const float* __restrict__ Cb) {
    __shared__ float sA[48];
    __shared__ float sM[96];
    setup_shared(Ab, Cb, sA, sM);

    int tid = blockIdx.x * blockDim.x + threadIdx.x;
    int k = tid / B_;
    int b = tid - k * B_;
    int t0 = k * CL;

    int db = (k * 4) * B_ + b;
    float4 m4 = g_fb[db];
    float m[4] = {m4.x, m4.y, m4.z, m4.w};
    float P[16]; unpack_sym10(g_fb[db+B_], g_fb[db+2*B_], g_fb[db+3*B_], P);

    float M[16], cc[4], EE[16];

#pragma unroll 1
    for (int s = 0; s < CL; s++) {
        int t = t0 + s;
        float u[4], Ai[16], Cr[16];
        load_pre(t, b, sA, sM, u, Ai, Cr);

        // filter step (exact reference recursion, info form)
        float zh[4]; mv4(Ai, m, zh);
        float AP[16]; mm4(Ai, P, AP);
        float Ph[16]; mmT4_symf(AP, Ai, Ph);
        Ph[0] += QD; Ph[5] += QD; Ph[10] += QD; Ph[15] += QD;
        float Phi[16]; syminv4(Ph, Phi);
        float Ms[16];
#pragma unroll
        for (int i = 0; i < 16; i++) Ms[i] = Phi[i] + Cr[i];
        float W[16]; syminv4(Ms, W);
        float y[4]; mv4(Cr, zh, y);
#pragma unroll
        for (int i = 0; i < 4; i++) y[i] = u[i] - y[i];
        float dz[4]; mv4(W, y, dz);
        float pz[4];
#pragma unroll
        for (int i = 0; i < 4; i++) pz[i] = zh[i] + dz[i];

        int fb = (t * 4) * B_ + b;
        g_fwd[fb + 0*B_] = make_float4(pz[0], pz[1], pz[2], pz[3]);
        g_fwd[fb + 1*B_] = make_float4(W[0],  W[1],  W[2],  W[3]);
        g_fwd[fb + 2*B_] = make_float4(W[5],  W[6],  W[7],  W[10]);
        g_fwd[fb + 3*B_] = make_float4(W[11], W[15], 0.f,  0.f);

#pragma unroll
        for (int i = 0; i < 4; i++)  m[i] = pz[i];
#pragma unroll
        for (int i = 0; i < 16; i++) P[i] = W[i];

        if (k != 0) {      // chunk 0's smoother map is never applied
            float D[16], c[4], E[16];
            make_DcE(t, b, sA, pz, W, D, c, E);
            if (s == 0) {
#pragma unroll
                for (int i = 0; i < 16; i++) { M[i] = D[i]; EE[i] = E[i]; }
#pragma unroll
                for (int i = 0; i < 4; i++) cc[i] = c[i];
            } else {
                float tv[4]; mv4(M, c, tv);
#pragma unroll
                for (int i = 0; i < 4; i++) cc[i] += tv[i];
                float X[16]; mm4(M, E, X);
                float Y[16]; mmT4_symf(X, M, Y);
#pragma unroll
                for (int i = 0; i < 16; i++) EE[i] += Y[i];
                float Mn[16]; mm4(M, D, Mn);
#pragma unroll
                for (int i = 0; i < 16; i++) M[i] = Mn[i];
            }
        }
    }

    if (k != 0) {
        int cb = (k * 8) * B_ + b;
        g_ch[cb + 0*B_] = make_float4(M[0],  M[1],  M[2],  M[3]);
        g_ch[cb + 1*B_] = make_float4(M[4],  M[5],  M[6],  M[7]);
        g_ch[cb + 2*B_] = make_float4(M[8],  M[9],  M[10], M[11]);
        g_ch[cb + 3*B_] = make_float4(M[12], M[13], M[14], M[15]);
        g_ch[cb + 4*B_] = make_float4(cc[0], cc[1], cc[2], cc[3]);
        g_ch[cb + 5*B_] = make_float4(EE[0], EE[1], EE[2], EE[3]);
        g_ch[cb + 6*B_] = make_float4(EE[5], EE[6], EE[7], EE[10]);
        g_ch[cb + 7*B_] = make_float4(EE[11], EE[15], 0.f, 0.f);
    }
}

// ---------------------------------------------------------------------------
// Kernel 5: Kogge-Stone warp scan of smoother chunk maps (reverse).
// Lane k holds Map_{k+1} (lane 31: identity). After the scan,
// acc_k = Map_{k+1} ∘ ... ∘ Map_{31}; applied to (0,0) that is (c, E) ==
// the smoothed value entering chunk k.
// ---------------------------------------------------------------------------
__global__ void sboundary_ks_kernel() {
    int lane = threadIdx.x & 31;
    int b = (blockIdx.x * blockDim.x + threadIdx.x) >> 5;

    float M[16], c[4], E[16];
    if (lane == 31) {
#pragma unroll
        for (int i = 0; i < 16; i++) {
            M[i] = (i % 5 == 0) ? 1.0f : 0.0f;
            E[i] = 0.f;
        }
#pragma unroll
        for (int i = 0; i < 4; i++) c[i] = 0.f;
    } else {
        int cb = ((lane + 1) * 8) * B_ + b;
        unpack_rows(g_ch[cb], g_ch[cb+B_], g_ch[cb+2*B_], g_ch[cb+3*B_], M);
        float4 cf = g_ch[cb+4*B_];
        c[0]=cf.x; c[1]=cf.y; c[2]=cf.z; c[3]=cf.w;
        unpack_sym10(g_ch[cb+5*B_], g_ch[cb+6*B_], g_ch[cb+7*B_], E);
    }

#pragma unroll
    for (int d = 1; d < 32; d <<= 1) {
        float oM[16], oc[4], oE[16];
#pragma unroll
        for (int i = 0; i < 16; i++) {
            oM[i] = __shfl_down_sync(0xffffffffu, M[i], d);
            oE[i] = __shfl_down_sync(0xffffffffu, E[i], d);
        }
#pragma unroll
        for (int i = 0; i < 4; i++)
            oc[i] = __shfl_down_sync(0xffffffffu, c[i], d);
        if (lane + d < 32) {
            // acc = acc ∘ other  (other applied first):
            // E += M oE M^T ; c += M oc ; M = M oM
            float X[16]; mm4(M, oE, X);
            float Y[16]; mmT4_symf(X, M, Y);
#pragma unroll
            for (int i = 0; i < 16; i++) E[i] += Y[i];
            float tv[4]; mv4(M, oc, tv);
#pragma unroll
            for (int i = 0; i < 4; i++) c[i] += tv[i];
            float Mn[16]; mm4(M, oM, Mn);
#pragma unroll
            for (int i = 0; i < 16; i++) M[i] = Mn[i];
        }
    }

    int db = (lane * 5) * B_ + b;
    g_bd[db + 0*B_] = make_float4(c[0], c[1], c[2], c[3]);
    g_bd[db + 1*B_] = make_float4(E[0],  E[1],  E[2],  E[3]);
    g_bd[db + 2*B_] = make_float4(E[4],  E[5],  E[6],  E[7]);
    g_bd[db + 3*B_] = make_float4(E[8],  E[9],  E[10], E[11]);
    g_bd[db + 4*B_] = make_float4(E[12], E[13], E[14], E[15]);
}

// ---------------------------------------------------------------------------
// Kernel 6: final smoothing pass — recompute per-step maps, apply descending,
// write outputs.
// ---------------------------------------------------------------------------
__global__ void __launch_bounds__(128, 3)
sfinal_kernel(const float* __restrict__ Ab, float* __restrict__ out) {
    __shared__ float sA[48];
    for (int i = threadIdx.x; i < 48; i += blockDim.x) sA[i] = Ab[i];
    __syncthreads();

    int tid = blockIdx.x * blockDim.x + threadIdx.x;
    int k = tid / B_;
    int b = tid - k * B_;

    int db = (k * 5) * B_ + b;
    float4 z4 = g_bd[db];
    float z[4] = {z4.x, z4.y, z4.z, z4.w};
    float S[16];
    unpack_rows(g_bd[db + B_], g_bd[db + 2*B_], g_bd[db + 3*B_], g_bd[db + 4*B_], S);

    float* osb = out + (size_t)B_ * T_ * 4;
#pragma unroll 1
    for (int s = CL - 1; s >= 0; s--) {
        int t = k * CL + s;
        int fb = (t * 4) * B_ + b;
        float4 f0 = g_fwd[fb];
        float pz[4] = {f0.x, f0.y, f0.z, f0.w};
        float W[16]; unpack_sym10(g_fwd[fb+B_], g_fwd[fb+2*B_], g_fwd[fb+3*B_], W);

        float D[16], c[4], E[16];
        make_DcE(t, b, sA, pz, W, D, c, E);

        float nz[4]; mv4(D, z, nz);
        z[0] = nz[0] + c[0]; z[1] = nz[1] + c[1]; z[2] = nz[2] + c[2]; z[3] = nz[3] + c[3];
        float X[16]; mm4(D, S, X);
        float Y[16]; mmT4_symf(X, D, Y);
#pragma unroll
        for (int i = 0; i < 16; i++) S[i] = Y[i] + E[i];

        *reinterpret_cast<float4*>(out + ((size_t)b * T_ + t) * 4) =
            make_float4(z[0], z[1], z[2], z[3]);
        float* op = osb + ((size_t)b * T_ + t) * 16;
        reinterpret_cast<float4*>(op)[0] = make_float4(S[0],  S[1],  S[2],  S[3]);
        reinterpret_cast<float4*>(op)[1] = make_float4(S[4],  S[5],  S[6],  S[7]);
        reinterpret_cast<float4*>(op)[2] = make_float4(S[8],  S[9],  S[10], S[11]);
        reinterpret_cast<float4*>(op)[3] = make_float4(S[12], S[13], S[14], S[15]);
    }
}

// ---------------------------------------------------------------------------
extern "C" void kernel_launch(void* const* d_in, const int* in_sizes, int n_in,
                              void* d_out, int out_size) {
    const float* a  = (const float*)d_in[0];   // [B,T,20]
    const float* lg = (const float*)d_in[1];   // [B,T,3]
    const float* Ab = (const float*)d_in[2];   // [3,4,4]
    const float* Cb = (const float*)d_in[3];   // [3,20,4]
    float* out = (float*)d_out;

    pre_kernel<<<(B_ * T_) / 256, 256>>>(a, lg, Cb);
    fchunk_kernel<<<((NCH - 1) * B_) / 128, 128>>>(Ab, Cb);
    fboundary_ks_kernel<<<(B_ * 32) / 128, 128>>>();
    ffinal_schunk_kernel<<<(NCH * B_) / 128, 128>>>(Ab, Cb);
    sboundary_ks_kernel<<<(B_ * 32) / 128, 128>>>();
    sfinal_kernel<<<(NCH * B_) / 128, 128>>>(Ab, out);
}

// round 17
// speedup vs baseline: 1.2083x; 1.2083x over previous
#include <cuda_runtime.h>
#include <math.h>

// Problem constants
#define B_   2048
#define T_   256
#define DA_  20
#define NCH  16      // number of time chunks (== segment lanes in boundary scans)
#define CL   16      // chunk length (NCH*CL == T_)

#define QD   0.08f
#define RINV (1.0f/0.03f)

// Scratch (static __device__ globals). Packed float4, layout [t][group][b]
// so warp lanes (consecutive b) give coalesced 128B transactions.
__device__ float4 g_ua [T_ * 2 * B_];    // 0 = u/R | 1 = (a0,a1,a2,0)              (16 MB)
__device__ float4 g_fc [NCH * 12 * B_];  // fwd chunk element: A rows(4), b(1), C sym(3), eta(1), J sym(3)
__device__ float4 g_fb [NCH * 4 * B_];   // fwd boundary state: m(1), P sym(3)
__device__ float4 g_fwd[T_ * 4 * B_];    // 0=post_z | 1-3=post_std sym10+pad       (32 MB)
__device__ float4 g_ch [NCH * 8 * B_];   // smoother chunk map: M rows(4), c(1), E sym(3)
__device__ float4 g_bd [NCH * 5 * B_];   // smoother boundary: z(1), S rows(4)

// ---------------------------------------------------------------------------
// 4x4 helpers (row-major flat)
// ---------------------------------------------------------------------------
__device__ __forceinline__ void mm4(const float* A, const float* B, float* C) {
#pragma unroll
    for (int i = 0; i < 4; i++)
#pragma unroll
        for (int j = 0; j < 4; j++) {
            float s = A[i*4+0] * B[0*4+j];
            s = fmaf(A[i*4+1], B[1*4+j], s);
            s = fmaf(A[i*4+2], B[2*4+j], s);
            s = fmaf(A[i*4+3], B[3*4+j], s);
            C[i*4+j] = s;
        }
}

// C = A * B^T, result known symmetric: upper triangle + mirror.
__device__ __forceinline__ void mmT4_symf(const float* A, const float* B, float* C) {
#pragma unroll
    for (int i = 0; i < 4; i++)
#pragma unroll
        for (int j = i; j < 4; j++) {
            float s = A[i*4+0] * B[j*4+0];
            s = fmaf(A[i*4+1], B[j*4+1], s);
            s = fmaf(A[i*4+2], B[j*4+2], s);
            s = fmaf(A[i*4+3], B[j*4+3], s);
            C[i*4+j] = s;
        }
    C[4]  = C[1];  C[8]  = C[2];  C[12] = C[3];
    C[9]  = C[6];  C[13] = C[7];  C[14] = C[11];
}

// C = A^T * U, result known symmetric.
__device__ __forceinline__ void mtm_sym(const float* A, const float* U, float* C) {
#pragma unroll
    for (int i = 0; i < 4; i++)
#pragma unroll
        for (int j = i; j < 4; j++) {
            float s = A[0*4+i] * U[0*4+j];
            s = fmaf(A[1*4+i], U[1*4+j], s);
            s = fmaf(A[2*4+i], U[2*4+j], s);
            s = fmaf(A[3*4+i], U[3*4+j], s);
            C[i*4+j] = s;
        }
    C[4]  = C[1];  C[8]  = C[2];  C[12] = C[3];
    C[9]  = C[6];  C[13] = C[7];  C[14] = C[11];
}

__device__ __forceinline__ void mv4(const float* A, const float* x, float* y) {
#pragma unroll
    for (int i = 0; i < 4; i++) {
        float s = A[i*4+0] * x[0];
        s = fmaf(A[i*4+1], x[1], s);
        s = fmaf(A[i*4+2], x[2], s);
        s = fmaf(A[i*4+3], x[3], s);
        y[i] = s;
    }
}

// y = A^T x
__device__ __forceinline__ void mvT4(const float* A, const float* x, float* y) {
#pragma unroll
    for (int i = 0; i < 4; i++) {
        float s = A[0*4+i] * x[0];
        s = fmaf(A[1*4+i], x[1], s);
        s = fmaf(A[2*4+i], x[2], s);
        s = fmaf(A[3*4+i], x[3], s);
        y[i] = s;
    }
}

// General branch-free 4x4 inverse via 2x2 sub-determinants.
__device__ __forceinline__ void inv4(const float* a, float* inv) {
    float b00 = a[0]*a[5]  - a[1]*a[4];
    float b01 = a[0]*a[6]  - a[2]*a[4];
    float b02 = a[0]*a[7]  - a[3]*a[4];
    float b03 = a[1]*a[6]  - a[2]*a[5];
    float b04 = a[1]*a[7]  - a[3]*a[5];
    float b05 = a[2]*a[7]  - a[3]*a[6];
    float b06 = a[8]*a[13] - a[9]*a[12];
    float b07 = a[8]*a[14] - a[10]*a[12];
    float b08 = a[8]*a[15] - a[11]*a[12];
    float b09 = a[9]*a[14] - a[10]*a[13];
    float b10 = a[9]*a[15] - a[11]*a[13];
    float b11 = a[10]*a[15]- a[11]*a[14];
    float det = b00*b11 - b01*b10 + b02*b09 + b03*b08 - b04*b07 + b05*b06;
    float id = 1.0f / det;
    inv[0]  = (a[5]*b11  - a[6]*b10  + a[7]*b09 ) * id;
    inv[1]  = (a[2]*b10  - a[1]*b11  - a[3]*b09 ) * id;
    inv[2]  = (a[13]*b05 - a[14]*b04 + a[15]*b03) * id;
    inv[3]  = (a[10]*b04 - a[9]*b05  - a[11]*b03) * id;
    inv[4]  = (a[6]*b08  - a[4]*b11  - a[7]*b07 ) * id;
    inv[5]  = (a[0]*b11  - a[2]*b08  + a[3]*b07 ) * id;
    inv[6]  = (a[14]*b02 - a[12]*b05 - a[15]*b01) * id;
    inv[7]  = (a[8]*b05  - a[10]*b02 + a[11]*b01) * id;
    inv[8]  = (a[4]*b10  - a[5]*b08  + a[7]*b06 ) * id;
    inv[9]  = (a[1]*b08  - a[0]*b10  - a[3]*b06 ) * id;
    inv[10] = (a[12]*b04 - a[13]*b02 + a[15]*b00) * id;
    inv[11] = (a[9]*b02  - a[8]*b04  - a[11]*b00) * id;
    inv[12] = (a[5]*b07  - a[4]*b09  - a[6]*b06 ) * id;
    inv[13] = (a[0]*b09  - a[1]*b07  + a[2]*b06 ) * id;
    inv[14] = (a[13]*b01 - a[12]*b03 - a[14]*b00) * id;
    inv[15] = (a[8]*b03  - a[9]*b01  + a[10]*b00) * id;
}

// SPD 4x4 inverse via 2x2 block Schur complement.
__device__ __forceinline__ void syminv4(const float* a, float* r) {
    float dP  = fmaf(a[0], a[5], -a[1]*a[1]);
    float idP = 1.0f / dP;
    float p00 =  a[5]*idP, p01 = -a[1]*idP, p11 = a[0]*idP;
    float t00 = fmaf(p00, a[2], p01*a[6]);
    float t01 = fmaf(p00, a[3], p01*a[7]);
    float t10 = fmaf(p01, a[2], p11*a[6]);
    float t11 = fmaf(p01, a[3], p11*a[7]);
    float s00 = a[10] - fmaf(a[2], t00, a[6]*t10);
    float s01 = a[11] - fmaf(a[2], t01, a[6]*t11);
    float s11 = a[15] - fmaf(a[3], t01, a[7]*t11);
    float dS  = fmaf(s00, s11, -s01*s01);
    float idS = 1.0f / dS;
    float w00 = s11*idS, w01 = -s01*idS, w11 = s00*idS;
    float u00 = fmaf(t00, w00, t01*w01);
    float u01 = fmaf(t00, w01, t01*w11);
    float u10 = fmaf(t10, w00, t11*w01);
    float u11 = fmaf(t10, w01, t11*w11);
    float x00 = p00 + fmaf(u00, t00, u01*t01);
    float x01 = p01 + fmaf(u00, t10, u01*t11);
    float x11 = p11 + fmaf(u10, t10, u11*t11);
    r[0]=x00;  r[1]=x01;  r[4]=x01;  r[5]=x11;
    r[2]=-u00; r[3]=-u01; r[6]=-u10; r[7]=-u11;
    r[8]=-u00; r[9]=-u10; r[12]=-u01; r[13]=-u11;
    r[10]=w00; r[11]=w01; r[14]=w01; r[15]=w11;
}

__device__ __forceinline__ void unpack_sym10(float4 f1, float4 f2, float4 f3, float* M) {
    M[0]=f1.x;  M[1]=f1.y;  M[2]=f1.z;  M[3]=f1.w;
    M[4]=f1.y;  M[5]=f2.x;  M[6]=f2.y;  M[7]=f2.z;
    M[8]=f1.z;  M[9]=f2.y;  M[10]=f2.w; M[11]=f3.x;
    M[12]=f1.w; M[13]=f2.z; M[14]=f3.x; M[15]=f3.y;
}

__device__ __forceinline__ void unpack_rows(float4 r0, float4 r1, float4 r2, float4 r3, float* M) {
    M[0]=r0.x;  M[1]=r0.y;  M[2]=r0.z;  M[3]=r0.w;
    M[4]=r1.x;  M[5]=r1.y;  M[6]=r1.z;  M[7]=r1.w;
    M[8]=r2.x;  M[9]=r2.y;  M[10]=r2.z; M[11]=r2.w;
    M[12]=r3.x; M[13]=r3.y; M[14]=r3.z; M[15]=r3.w;
}

// ---------------------------------------------------------------------------
// Shared-memory setup for consumers: sA = A_base (48), sM = 6 Gram combos (96)
// ---------------------------------------------------------------------------
__device__ __forceinline__ void setup_shared(const float* __restrict__ Ab,
                                             const float* __restrict__ Cb,
                                             float* sA, float* sM) {
    for (int i = threadIdx.x; i < 48; i += blockDim.x) sA[i] = Ab[i];
    if (threadIdx.x < 96) {
        int e = threadIdx.x;
        int m = e >> 4, idx = e & 15, j1 = idx >> 2, j2 = idx & 3;
        int k, l;
        switch (m) {
            case 0: k=0; l=0; break;  case 1: k=1; l=1; break;
            case 2: k=2; l=2; break;  case 3: k=0; l=1; break;
            case 4: k=0; l=2; break;  default: k=1; l=2; break;
        }
        float s = 0.0f;
        for (int i = 0; i < DA_; i++)
            s = fmaf(Cb[k*80+i*4+j1], Cb[l*80+i*4+j2], s);
        if (k != l)
            for (int i = 0; i < DA_; i++)
                s = fmaf(Cb[l*80+i*4+j1], Cb[k*80+i*4+j2], s);
        sM[e] = s;
    }
    __syncthreads();
}

// Reconstruct Ai from alphas.
__device__ __forceinline__ void make_Ai(const float* sA, float a0, float a1, float a2, float* Ai) {
#pragma unroll
    for (int i = 0; i < 16; i++)
        Ai[i] = fmaf(a0, sA[i], fmaf(a1, sA[16+i], a2 * sA[32+i]));
}

// Reconstruct Cr (symmetric) from alphas.
__device__ __forceinline__ void make_Cr(const float* sM, float a0, float a1, float a2, float* Cr) {
    float c0 = a0*a0*RINV, c1 = a1*a1*RINV, c2 = a2*a2*RINV;
    float c3 = a0*a1*RINV, c4 = a0*a2*RINV, c5 = a1*a2*RINV;
    const int SI[10] = {0, 1, 2, 3, 5, 6, 7, 10, 11, 15};
#pragma unroll
    for (int u = 0; u < 10; u++) {
        int i = SI[u];
        Cr[i] = fmaf(c0, sM[i],
                fmaf(c1, sM[16+i],
                fmaf(c2, sM[32+i],
                fmaf(c3, sM[48+i],
                fmaf(c4, sM[64+i], c5 * sM[80+i])))));
    }
    Cr[4]  = Cr[1];  Cr[8]  = Cr[2];  Cr[12] = Cr[3];
    Cr[9]  = Cr[6];  Cr[13] = Cr[7];  Cr[14] = Cr[11];
}

// Load (u, Ai, Cr) for (t, b): 32B load + on-the-fly reconstruction.
__device__ __forceinline__ void load_pre(int t, int b, const float* sA, const float* sM,
                                         float* u, float* Ai, float* Cr) {
    int base = (t * 2) * B_ + b;
    float4 u4 = g_ua[base];
    float4 a4 = g_ua[base + B_];
    u[0]=u4.x; u[1]=u4.y; u[2]=u4.z; u[3]=u4.w;
    make_Ai(sA, a4.x, a4.y, a4.z, Ai);
    make_Cr(sM, a4.x, a4.y, a4.z, Cr);
}

// ---------------------------------------------------------------------------
// Kernel 1: per-(b,t): softmax, u = C^T a / R  (compressed 32B output)
// ---------------------------------------------------------------------------
__global__ void pre_kernel(const float* __restrict__ a,
                           const float* __restrict__ lg,
                           const float* __restrict__ Cb) {
    __shared__ float sC[240];
    for (int i = threadIdx.x; i < 240; i += 256) sC[i] = Cb[i];
    __syncthreads();

    int tid = blockIdx.x * 256 + threadIdx.x;
    int t = tid / B_;
    int b = tid - t * B_;

    const float* lp = lg + ((size_t)b * T_ + t) * 3;
    float l0 = lp[0], l1 = lp[1], l2 = lp[2];
    float mx = fmaxf(l0, fmaxf(l1, l2));
    float e0 = expf(l0 - mx), e1 = expf(l1 - mx), e2 = expf(l2 - mx);
    float is = 1.0f / (e0 + e1 + e2);
    float a0 = e0 * is, a1 = e1 * is, a2 = e2 * is;

    const float4* ap4 = reinterpret_cast<const float4*>(a + ((size_t)b * T_ + t) * DA_);
    float av[20];
#pragma unroll
    for (int q = 0; q < 5; q++) {
        float4 v = ap4[q];
        av[q*4+0] = v.x; av[q*4+1] = v.y; av[q*4+2] = v.z; av[q*4+3] = v.w;
    }
    float u0 = 0.f, u1 = 0.f, u2 = 0.f, u3 = 0.f;
#pragma unroll
    for (int i = 0; i < DA_; i++) {
        float w0 = fmaf(a0, sC[i*4+0], fmaf(a1, sC[80+i*4+0], a2 * sC[160+i*4+0]));
        float w1 = fmaf(a0, sC[i*4+1], fmaf(a1, sC[80+i*4+1], a2 * sC[160+i*4+1]));
        float w2 = fmaf(a0, sC[i*4+2], fmaf(a1, sC[80+i*4+2], a2 * sC[160+i*4+2]));
        float w3 = fmaf(a0, sC[i*4+3], fmaf(a1, sC[80+i*4+3], a2 * sC[160+i*4+3]));
        u0 = fmaf(av[i], w0, u0);
        u1 = fmaf(av[i], w1, u1);
        u2 = fmaf(av[i], w2, u2);
        u3 = fmaf(av[i], w3, u3);
    }

    int base = (t * 2) * B_ + b;
    g_ua[base + 0*B_] = make_float4(u0*RINV, u1*RINV, u2*RINV, u3*RINV);
    g_ua[base + 1*B_] = make_float4(a0, a1, a2, 0.f);
}

// ---------------------------------------------------------------------------
// Build forward-scan element (A, b, C, eta, J) for time t.
// ---------------------------------------------------------------------------
__device__ __forceinline__ void build_element(int t, int b,
        const float* sA, const float* sM,
        float* A, float* bb, float* C, float* eta, float* J) {
    float u[4], Ai[16], Cr[16];
    load_pre(t, b, sA, sM, u, Ai, Cr);

    if (t == 0) {
        float S[16]; mmT4_symf(Ai, Ai, S);      // Ai Ai^T
        float Ph[16];
#pragma unroll
        for (int i = 0; i < 16; i++) Ph[i] = 20.0f * S[i];
        Ph[0] += QD; Ph[5] += QD; Ph[10] += QD; Ph[15] += QD;
        float Phi[16]; syminv4(Ph, Phi);
        float Ms[16];
#pragma unroll
        for (int i = 0; i < 16; i++) Ms[i] = Phi[i] + Cr[i];
        float W[16]; syminv4(Ms, W);
        mv4(W, u, bb);
#pragma unroll
        for (int i = 0; i < 16; i++) { A[i] = 0.f; C[i] = W[i]; J[i] = 0.f; }
#pragma unroll
        for (int i = 0; i < 4; i++) eta[i] = 0.f;
        return;
    }

    float M[16];
#pragma unroll
    for (int i = 0; i < 16; i++) M[i] = QD * Cr[i];
    M[0] += 1.f; M[5] += 1.f; M[10] += 1.f; M[15] += 1.f;
    float G[16]; syminv4(M, G);

    float v[4]; mv4(G, u, v);
#pragma unroll
    for (int i = 0; i < 4; i++) bb[i] = QD * v[i];
    mm4(G, Ai, A);
    mvT4(Ai, v, eta);
#pragma unroll
    for (int i = 0; i < 16; i++) C[i] = QD * G[i];
    float X[16]; mm4(G, Cr, X);
    float U[16]; mm4(X, Ai, U);
    mtm_sym(Ai, U, J);
}

// ---------------------------------------------------------------------------
// Compose: acc = acc (earlier) ⊗ e (later).   [Särkkä & García-Fernández]
// ---------------------------------------------------------------------------
__device__ __forceinline__ void compose_fwd(
        float* Ai_, float* bi, float* Ci, float* ni, float* Ji,      // acc (i)
        const float* Aj, const float* bj, const float* Cj,
        const float* nj, const float* Jj) {                          // elem (j)
    float M1[16]; mm4(Ci, Jj, M1);
    M1[0] += 1.f; M1[5] += 1.f; M1[10] += 1.f; M1[15] += 1.f;
    float dn[16]; inv4(M1, dn);
    float T1[16]; mm4(Aj, dn, T1);

    float An[16]; mm4(T1, Ai_, An);

    float w1[4]; mv4(Ci, nj, w1);
#pragma unroll
    for (int i = 0; i < 4; i++) w1[i] += bi[i];
    float bn[4]; mv4(T1, w1, bn);
#pragma unroll
    for (int i = 0; i < 4; i++) bn[i] += bj[i];

    float X[16]; mm4(T1, Ci, X);
    float Cn[16]; mmT4_symf(X, Aj, Cn);
#pragma unroll
    for (int i = 0; i < 16; i++) Cn[i] += Cj[i];

    // G = (I + Jj Ci)^-1 = I - Jj dn Ci
    float Y[16]; mm4(Jj, dn, Y);
    float G[16]; mm4(Y, Ci, G);
#pragma unroll
    for (int i = 0; i < 16; i++) G[i] = -G[i];
    G[0] += 1.f; G[5] += 1.f; G[10] += 1.f; G[15] += 1.f;

    float w2[4]; mv4(Jj, bi, w2);
#pragma unroll
    for (int i = 0; i < 4; i++) w2[i] = nj[i] - w2[i];
    float w3[4]; mv4(G, w2, w3);
    float nn[4]; mvT4(Ai_, w3, nn);
#pragma unroll
    for (int i = 0; i < 4; i++) nn[i] += ni[i];

    float Z[16]; mm4(G, Jj, Z);
    float U[16]; mm4(Z, Ai_, U);
    float Jn[16]; mtm_sym(Ai_, U, Jn);
#pragma unroll
    for (int i = 0; i < 16; i++) Jn[i] += Ji[i];

#pragma unroll
    for (int i = 0; i < 16; i++) { Ai_[i] = An[i]; Ci[i] = Cn[i]; Ji[i] = Jn[i]; }
#pragma unroll
    for (int i = 0; i < 4; i++)  { bi[i] = bn[i]; ni[i] = nn[i]; }
}

// ---------------------------------------------------------------------------
// Kernel 2: compose the CL elements of each chunk. Chunk NCH-1's element is
// never consumed by the boundary scan, so only NCH-1 chunks are built.
// ---------------------------------------------------------------------------
__global__ void fchunk_kernel(const float* __restrict__ Ab,
                              const float* __restrict__ Cb) {
    __shared__ float sA[48];
    __shared__ float sM[96];
    setup_shared(Ab, Cb, sA, sM);

    int tid = blockIdx.x * blockDim.x + threadIdx.x;
    int k = tid / B_;                 // 0 .. NCH-2
    int b = tid - k * B_;
    int t0 = k * CL;

    float A[16], bb[4], C[16], eta[4], J[16];
    build_element(t0, b, sA, sM, A, bb, C, eta, J);
#pragma unroll 1
    for (int s = 1; s < CL; s++) {
        float Aj[16], bj[4], Cj[16], nj[4], Jj[16];
        build_element(t0 + s, b, sA, sM, Aj, bj, Cj, nj, Jj);
        compose_fwd(A, bb, C, eta, J, Aj, bj, Cj, nj, Jj);
    }

    int cb = (k * 12) * B_ + b;
    g_fc[cb + 0*B_]  = make_float4(A[0],  A[1],  A[2],  A[3]);
    g_fc[cb + 1*B_]  = make_float4(A[4],  A[5],  A[6],  A[7]);
    g_fc[cb + 2*B_]  = make_float4(A[8],  A[9],  A[10], A[11]);
    g_fc[cb + 3*B_]  = make_float4(A[12], A[13], A[14], A[15]);
    g_fc[cb + 4*B_]  = make_float4(bb[0], bb[1], bb[2], bb[3]);
    g_fc[cb + 5*B_]  = make_float4(C[0],  C[1],  C[2],  C[3]);
    g_fc[cb + 6*B_]  = make_float4(C[5],  C[6],  C[7],  C[10]);
    g_fc[cb + 7*B_]  = make_float4(C[11], C[15], 0.f,  0.f);
    g_fc[cb + 8*B_]  = make_float4(eta[0], eta[1], eta[2], eta[3]);
    g_fc[cb + 9*B_]  = make_float4(J[0],  J[1],  J[2],  J[3]);
    g_fc[cb + 10*B_] = make_float4(J[5],  J[6],  J[7],  J[10]);
    g_fc[cb + 11*B_] = make_float4(J[11], J[15], 0.f,  0.f);
}

// ---------------------------------------------------------------------------
// Kernel 3: segmented (width-16) Kogge-Stone scan over chunk elements ->
// state entering each chunk. Lane 0 of each segment holds the prior element
// (A=0, J=0, C=P0, b=m0); lane k (1..15) holds chunk k-1's element. After
// the inclusive scan, (b, C) at lane k IS the filtered state entering chunk k.
// ---------------------------------------------------------------------------
__global__ void fboundary_ks_kernel() {
    int lane = threadIdx.x & 15;                              // segment lane
    int b = (blockIdx.x * blockDim.x + threadIdx.x) >> 4;     // batch

    float A[16], bb[4], C[16], eta[4], J[16];
    if (lane == 0) {
#pragma unroll
        for (int i = 0; i < 16; i++) {
            A[i] = 0.f; J[i] = 0.f;
            C[i] = (i % 5 == 0) ? 20.0f : 0.0f;
        }
#pragma unroll
        for (int i = 0; i < 4; i++) { bb[i] = 0.f; eta[i] = 0.f; }
    } else {
        int cb = ((lane - 1) * 12) * B_ + b;
        unpack_rows(g_fc[cb], g_fc[cb+B_], g_fc[cb+2*B_], g_fc[cb+3*B_], A);
        float4 b4 = g_fc[cb+4*B_];
        bb[0]=b4.x; bb[1]=b4.y; bb[2]=b4.z; bb[3]=b4.w;
        unpack_sym10(g_fc[cb+5*B_], g_fc[cb+6*B_], g_fc[cb+7*B_], C);
        float4 n4 = g_fc[cb+8*B_];
        eta[0]=n4.x; eta[1]=n4.y; eta[2]=n4.z; eta[3]=n4.w;
        unpack_sym10(g_fc[cb+9*B_], g_fc[cb+10*B_], g_fc[cb+11*B_], J);
    }

#pragma unroll
    for (int d = 1; d < 16; d <<= 1) {
        float oA[16], ob[4], oC[16], oe[4], oJ[16];
#pragma unroll
        for (int i = 0; i < 16; i++) {
            oA[i] = __shfl_up_sync(0xffffffffu, A[i], d, 16);
            oC[i] = __shfl_up_sync(0xffffffffu, C[i], d, 16);
            oJ[i] = __shfl_up_sync(0xffffffffu, J[i], d, 16);
        }
#pragma unroll
        for (int i = 0; i < 4; i++) {
            ob[i] = __shfl_up_sync(0xffffffffu, bb[i], d, 16);
            oe[i] = __shfl_up_sync(0xffffffffu, eta[i], d, 16);
        }
        if (lane >= d) {
            compose_fwd(oA, ob, oC, oe, oJ, A, bb, C, eta, J);
#pragma unroll
            for (int i = 0; i < 16; i++) { A[i] = oA[i]; C[i] = oC[i]; J[i] = oJ[i]; }
#pragma unroll
            for (int i = 0; i < 4; i++)  { bb[i] = ob[i]; eta[i] = oe[i]; }
        }
    }

    // state entering chunk `lane`: m = bb, P = C
    int db = (lane * 4) * B_ + b;
    g_fb[db + 0*B_] = make_float4(bb[0], bb[1], bb[2], bb[3]);
    g_fb[db + 1*B_] = make_float4(C[0],  C[1],  C[2],  C[3]);
    g_fb[db + 2*B_] = make_float4(C[5],  C[6],  C[7],  C[10]);
    g_fb[db + 3*B_] = make_float4(C[11], C[15], 0.f,  0.f);
}

// ---------------------------------------------------------------------------
// Smoother step coefficients from (pz_t, W_t, alpha_{t+1}):
//   z_s(t) = D z_s(t+1) + c ;  S_s(t) = D S_s(t+1) D^T + E
// ---------------------------------------------------------------------------
__device__ __forceinline__ void make_DcE(int t, int b, const float* sA,
        const float* pz, const float* W, float* D, float* c, float* E) {
    if (t == T_ - 1) {
#pragma unroll
        for (int i = 0; i < 16; i++) { D[i] = 0.f; E[i] = W[i]; }
#pragma unroll
        for (int i = 0; i < 4; i++) c[i] = pz[i];
        return;
    }
    float4 a4 = g_ua[((t + 1) * 2 + 1) * B_ + b];
    float Ai1[16]; make_Ai(sA, a4.x, a4.y, a4.z, Ai1);

    float APs[16]; mm4(Ai1, W, APs);
    float shn[16]; mmT4_symf(APs, Ai1, shn);
    shn[0] += QD; shn[5] += QD; shn[10] += QD; shn[15] += QD;
#pragma unroll
    for (int i = 0; i < 16; i++)
        shn[i] = fmaxf(shn[i], (i % 5 == 0) ? 1e-4f : 0.0f);

    float iv[16]; inv4(shn, iv);
    // D = W Ai1^T iv = APs^T iv
#pragma unroll
    for (int i = 0; i < 4; i++)
#pragma unroll
        for (int j = 0; j < 4; j++) {
            float s = APs[0*4+i] * iv[0*4+j];
            s = fmaf(APs[1*4+i], iv[1*4+j], s);
            s = fmaf(APs[2*4+i], iv[2*4+j], s);
            s = fmaf(APs[3*4+i], iv[3*4+j], s);
            D[i*4+j] = s;
        }
    float zhn[4]; mv4(Ai1, pz, zhn);
    float tz[4];  mv4(D, zhn, tz);
#pragma unroll
    for (int i = 0; i < 4; i++) c[i] = pz[i] - tz[i];

    float X[16]; mm4(D, shn, X);
    float Y[16]; mmT4_symf(X, D, Y);
#pragma unroll
    for (int i = 0; i < 16; i++) E[i] = W[i] - Y[i];
}

// ---------------------------------------------------------------------------
// Kernel 4 (fused): from chunk entry state run exact sequential filter steps,
// write (pz, W), and compose the smoother chunk affine map (skipped for
// chunk 0 -- its map is never applied).
// ---------------------------------------------------------------------------
__global__ void ffinal_schunk_kernel(const float* __restrict__ Ab,
                                     const float* __restrict__ Cb) {
    __shared__ float sA[48];
    __shared__ float sM[96];
    setup_shared(Ab, Cb, sA, sM);

    int tid = blockIdx.x * blockDim.x + threadIdx.x;
    int k = tid / B_;
    int b = tid - k * B_;
    int t0 = k * CL;

    int db = (k * 4) * B_ + b;
    float4 m4 = g_fb[db];
    float m[4] = {m4.x, m4.y, m4.z, m4.w};
    float P[16]; unpack_sym10(g_fb[db+B_], g_fb[db+2*B_], g_fb[db+3*B_], P);

    float M[16], cc[4], EE[16];

#pragma unroll 1
    for (int s = 0; s < CL; s++) {
        int t = t0 + s;
        float u[4], Ai[16], Cr[16];
        load_pre(t, b, sA, sM, u, Ai, Cr);

        // filter step (exact reference recursion, info form)
        float zh[4]; mv4(Ai, m, zh);
        float AP[16]; mm4(Ai, P, AP);
        float Ph[16]; mmT4_symf(AP, Ai, Ph);
        Ph[0] += QD; Ph[5] += QD; Ph[10] += QD; Ph[15] += QD;
        float Phi[16]; syminv4(Ph, Phi);
        float Ms[16];
#pragma unroll
        for (int i = 0; i < 16; i++) Ms[i] = Phi[i] + Cr[i];
        float W[16]; syminv4(Ms, W);
        float y[4]; mv4(Cr, zh, y);
#pragma unroll
        for (int i = 0; i < 4; i++) y[i] = u[i] - y[i];
        float dz[4]; mv4(W, y, dz);
        float pz[4];
#pragma unroll
        for (int i = 0; i < 4; i++) pz[i] = zh[i] + dz[i];

        int fb = (t * 4) * B_ + b;
        g_fwd[fb + 0*B_] = make_float4(pz[0], pz[1], pz[2], pz[3]);
        g_fwd[fb + 1*B_] = make_float4(W[0],  W[1],  W[2],  W[3]);
        g_fwd[fb + 2*B_] = make_float4(W[5],  W[6],  W[7],  W[10]);
        g_fwd[fb + 3*B_] = make_float4(W[11], W[15], 0.f,  0.f);

#pragma unroll
        for (int i = 0; i < 4; i++)  m[i] = pz[i];
#pragma unroll
        for (int i = 0; i < 16; i++) P[i] = W[i];

        if (k != 0) {      // chunk 0's smoother map is never applied
            float D[16], c[4], E[16];
            make_DcE(t, b, sA, pz, W, D, c, E);
            if (s == 0) {
#pragma unroll
                for (int i = 0; i < 16; i++) { M[i] = D[i]; EE[i] = E[i]; }
#pragma unroll
                for (int i = 0; i < 4; i++) cc[i] = c[i];
            } else {
                float tv[4]; mv4(M, c, tv);
#pragma unroll
                for (int i = 0; i < 4; i++) cc[i] += tv[i];
                float X[16]; mm4(M, E, X);
                float Y[16]; mmT4_symf(X, M, Y);
#pragma unroll
                for (int i = 0; i < 16; i++) EE[i] += Y[i];
                float Mn[16]; mm4(M, D, Mn);
#pragma unroll
                for (int i = 0; i < 16; i++) M[i] = Mn[i];
            }
        }
    }

    if (k != 0) {
        int cb = (k * 8) * B_ + b;
        g_ch[cb + 0*B_] = make_float4(M[0],  M[1],  M[2],  M[3]);
        g_ch[cb + 1*B_] = make_float4(M[4],  M[5],  M[6],  M[7]);
        g_ch[cb + 2*B_] = make_float4(M[8],  M[9],  M[10], M[11]);
        g_ch[cb + 3*B_] = make_float4(M[12], M[13], M[14], M[15]);
        g_ch[cb + 4*B_] = make_float4(cc[0], cc[1], cc[2], cc[3]);
        g_ch[cb + 5*B_] = make_float4(EE[0], EE[1], EE[2], EE[3]);
        g_ch[cb + 6*B_] = make_float4(EE[5], EE[6], EE[7], EE[10]);
        g_ch[cb + 7*B_] = make_float4(EE[11], EE[15], 0.f, 0.f);
    }
}

// ---------------------------------------------------------------------------
// Kernel 5: segmented (width-16) Kogge-Stone scan of smoother chunk maps,
// reverse direction. Lane k holds Map_{k+1} (lane 15: identity). After the
// scan, acc_k = Map_{k+1} ∘ ... ∘ Map_{15}; applied to (0,0), (c, E) is the
// smoothed value entering chunk k.
// ---------------------------------------------------------------------------
__global__ void sboundary_ks_kernel() {
    int lane = threadIdx.x & 15;
    int b = (blockIdx.x * blockDim.x + threadIdx.x) >> 4;

    float M[16], c[4], E[16];
    if (lane == 15) {
#pragma unroll
        for (int i = 0; i < 16; i++) {
            M[i] = (i % 5 == 0) ? 1.0f : 0.0f;
            E[i] = 0.f;
        }
#pragma unroll
        for (int i = 0; i < 4; i++) c[i] = 0.f;
    } else {
        int cb = ((lane + 1) * 8) * B_ + b;
        unpack_rows(g_ch[cb], g_ch[cb+B_], g_ch[cb+2*B_], g_ch[cb+3*B_], M);
        float4 cf = g_ch[cb+4*B_];
        c[0]=cf.x; c[1]=cf.y; c[2]=cf.z; c[3]=cf.w;
        unpack_sym10(g_ch[cb+5*B_], g_ch[cb+6*B_], g_ch[cb+7*B_], E);
    }

#pragma unroll
    for (int d = 1; d < 16; d <<= 1) {
        float oM[16], oc[4], oE[16];
#pragma unroll
        for (int i = 0; i < 16; i++) {
            oM[i] = __shfl_down_sync(0xffffffffu, M[i], d, 16);
            oE[i] = __shfl_down_sync(0xffffffffu, E[i], d, 16);
        }
#pragma unroll
        for (int i = 0; i < 4; i++)
            oc[i] = __shfl_down_sync(0xffffffffu, c[i], d, 16);
        if (lane + d < 16) {
            // acc = acc ∘ other (other applied first):
            // E += M oE M^T ; c += M oc ; M = M oM
            float X[16]; mm4(M, oE, X);
            float Y[16]; mmT4_symf(X, M, Y);
#pragma unroll
            for (int i = 0; i < 16; i++) E[i] += Y[i];
            float tv[4]; mv4(M, oc, tv);
#pragma unroll
            for (int i = 0; i < 4; i++) c[i] += tv[i];
            float Mn[16]; mm4(M, oM, Mn);
#pragma unroll
            for (int i = 0; i < 16; i++) M[i] = Mn[i];
        }
    }

    int db = (lane * 5) * B_ + b;
    g_bd[db + 0*B_] = make_float4(c[0], c[1], c[2], c[3]);
    g_bd[db + 1*B_] = make_float4(E[0],  E[1],  E[2],  E[3]);
    g_bd[db + 2*B_] = make_float4(E[4],  E[5],  E[6],  E[7]);
    g_bd[db + 3*B_] = make_float4(E[8],  E[9],  E[10], E[11]);
    g_bd[db + 4*B_] = make_float4(E[12], E[13], E[14], E[15]);
}

// ---------------------------------------------------------------------------
// Kernel 6: final smoothing pass — recompute per-step maps, apply descending,
// write outputs.
// ---------------------------------------------------------------------------
__global__ void sfinal_kernel(const float* __restrict__ Ab,
                              float* __restrict__ out) {
    __shared__ float sA[48];
    for (int i = threadIdx.x; i < 48; i += blockDim.x) sA[i] = Ab[i];
    __syncthreads();

    int tid = blockIdx.x * blockDim.x + threadIdx.x;
    int k = tid / B_;
    int b = tid - k * B_;

    int db = (k * 5) * B_ + b;
    float4 z4 = g_bd[db];
    float z[4] = {z4.x, z4.y, z4.z, z4.w};
    float S[16];
    unpack_rows(g_bd[db + B_], g_bd[db + 2*B_], g_bd[db + 3*B_], g_bd[db + 4*B_], S);

    float* osb = out + (size_t)B_ * T_ * 4;
#pragma unroll 1
    for (int s = CL - 1; s >= 0; s--) {
        int t = k * CL + s;
        int fb = (t * 4) * B_ + b;
        float4 f0 = g_fwd[fb];
        float pz[4] = {f0.x, f0.y, f0.z, f0.w};
        float W[16]; unpack_sym10(g_fwd[fb+B_], g_fwd[fb+2*B_], g_fwd[fb+3*B_], W);

        float D[16], c[4], E[16];
        make_DcE(t, b, sA, pz, W, D, c, E);

        float nz[4]; mv4(D, z, nz);
        z[0] = nz[0] + c[0]; z[1] = nz[1] + c[1]; z[2] = nz[2] + c[2]; z[3] = nz[3] + c[3];
        float X[16]; mm4(D, S, X);
        float Y[16]; mmT4_symf(X, D, Y);
#pragma unroll
        for (int i = 0; i < 16; i++) S[i] = Y[i] + E[i];

        *reinterpret_cast<float4*>(out + ((size_t)b * T_ + t) * 4) =
            make_float4(z[0], z[1], z[2], z[3]);
        float* op = osb + ((size_t)b * T_ + t) * 16;
        reinterpret_cast<float4*>(op)[0] = make_float4(S[0],  S[1],  S[2],  S[3]);
        reinterpret_cast<float4*>(op)[1] = make_float4(S[4],  S[5],  S[6],  S[7]);
        reinterpret_cast<float4*>(op)[2] = make_float4(S[8],  S[9],  S[10], S[11]);
        reinterpret_cast<float4*>(op)[3] = make_float4(S[12], S[13], S[14], S[15]);
    }
}

// ---------------------------------------------------------------------------
extern "C" void kernel_launch(void* const* d_in, const int* in_sizes, int n_in,
                              void* d_out, int out_size) {
    const float* a  = (const float*)d_in[0];   // [B,T,20]
    const float* lg = (const float*)d_in[1];   // [B,T,3]
    const float* Ab = (const float*)d_in[2];   // [3,4,4]
    const float* Cb = (const float*)d_in[3];   // [3,20,4]
    float* out = (float*)d_out;

    pre_kernel<<<(B_ * T_) / 256, 256>>>(a, lg, Cb);
    fchunk_kernel<<<((NCH - 1) * B_) / 128, 128>>>(Ab, Cb);
    fboundary_ks_kernel<<<(B_ * NCH) / 128, 128>>>();
    ffinal_schunk_kernel<<<(NCH * B_) / 128, 128>>>(Ab, Cb);
    sboundary_ks_kernel<<<(B_ * NCH) / 128, 128>>>();
    sfinal_kernel<<<(NCH * B_) / 128, 128>>>(Ab, out);
}